// round 5
// baseline (speedup 1.0000x reference)
#include <cuda_runtime.h>
#include <math.h>

#define BB 32
#define II 1024
#define CC 128
#define JJ 32
#define DD 64
#define JD 2048           // JJ*DD
#define NCHUNK 32
#define ICH (II/NCHUNK)   // 32 i's per chunk

// Scratch (device globals: no allocation in kernel_launch)
__device__ float g_uhat[(size_t)BB * II * JD];   // [b][i][j*64+d], 256 MiB
__device__ float g_spart[NCHUNK][BB * JD];       // partial s sums, 8 MiB
__device__ float g_b1[(size_t)BB * II * JJ];     // routing logits after agree1, 4 MiB
__device__ float g_v[BB * JD];                   // current v[b][j][d]

// ---------------------------------------------------------------------------
// tf32 helpers
// ---------------------------------------------------------------------------
__device__ __forceinline__ unsigned f2tf(float f) {
    unsigned r;
    asm("cvt.rna.tf32.f32 %0, %1;" : "=r"(r) : "f"(f));
    return r;
}

__device__ __forceinline__ void mma_tf32(float c[4],
                                         unsigned a0, unsigned a1, unsigned a2, unsigned a3,
                                         unsigned b0, unsigned b1) {
    asm volatile(
        "mma.sync.aligned.m16n8k8.row.col.f32.tf32.tf32.f32 "
        "{%0,%1,%2,%3}, {%4,%5,%6,%7}, {%8,%9}, {%0,%1,%2,%3};"
        : "+f"(c[0]), "+f"(c[1]), "+f"(c[2]), "+f"(c[3])
        : "r"(a0), "r"(a1), "r"(a2), "r"(a3), "r"(b0), "r"(b1));
}

// ---------------------------------------------------------------------------
// Kernel 1: u_hat GEMM, tf32x3 (error-compensated -> ~fp32 accuracy).
// Per block: one i, 256-wide jd tile, all 32 b. A (x slice) staged in smem
// split into hi/lo tf32 bits; B (W) streamed from global (read exactly once)
// with depth-1 register prefetch, split hi/lo in registers.
// ---------------------------------------------------------------------------
#define XSTR 132

__global__ void __launch_bounds__(256, 2)
gemm_kernel(const float* __restrict__ x, const float* __restrict__ W) {
    __shared__ unsigned xh[32 * XSTR];
    __shared__ unsigned xl[32 * XSTR];

    const int i    = blockIdx.y;
    const int jt   = blockIdx.x;          // 0..7 -> jd base = jt*256
    const int tid  = threadIdx.x;
    const int lane = tid & 31;
    const int warp = tid >> 5;

    // Stage x[:, i, :] split into tf32 hi/lo, row-major [b][c]
    for (int e = tid * 4; e < BB * CC; e += 1024) {
        int b = e >> 7, c = e & 127;
        float4 v = *(const float4*)(x + ((size_t)b * II + i) * CC + c);
        unsigned* oh = xh + b * XSTR + c;
        unsigned* ol = xl + b * XSTR + c;
        float f[4] = {v.x, v.y, v.z, v.w};
#pragma unroll
        for (int k = 0; k < 4; k++) {
            unsigned hi = f2tf(f[k]);
            oh[k] = hi;
            ol[k] = f2tf(f[k] - __uint_as_float(hi));
        }
    }
    __syncthreads();

    const int nbase = jt * 256 + warp * 32;   // this warp's jd base (32 wide)
    const float* Wp[4];
#pragma unroll
    for (int q = 0; q < 4; q++) {
        int n = nbase + q * 8 + (lane >> 2);
        int j = n >> 6, d = n & 63;
        Wp[q] = W + (((size_t)j * II + i) * DD + d) * CC + (lane & 3);
    }

    float acc[2][4][4] = {};
    float bf[2][4][2];
#pragma unroll
    for (int q = 0; q < 4; q++) { bf[0][q][0] = Wp[q][0]; bf[0][q][1] = Wp[q][4]; }

    const int arow = lane >> 2;
    const int acol = lane & 3;

#pragma unroll
    for (int s = 0; s < 16; s++) {
        const int cur = s & 1, nxt = cur ^ 1;
        if (s < 15) {
#pragma unroll
            for (int q = 0; q < 4; q++) {
                bf[nxt][q][0] = Wp[q][8 * (s + 1)];
                bf[nxt][q][1] = Wp[q][8 * (s + 1) + 4];
            }
        }
        unsigned ah[2][4], al[2][4];
#pragma unroll
        for (int mt = 0; mt < 2; mt++) {
            const int off = (mt * 16 + arow) * XSTR + s * 8 + acol;
            ah[mt][0] = xh[off];            al[mt][0] = xl[off];
            ah[mt][1] = xh[off + 8 * XSTR]; al[mt][1] = xl[off + 8 * XSTR];
            ah[mt][2] = xh[off + 4];        al[mt][2] = xl[off + 4];
            ah[mt][3] = xh[off + 8 * XSTR + 4]; al[mt][3] = xl[off + 8 * XSTR + 4];
        }
#pragma unroll
        for (int q = 0; q < 4; q++) {
            float f0 = bf[cur][q][0], f1 = bf[cur][q][1];
            unsigned bh0 = f2tf(f0), bh1 = f2tf(f1);
            unsigned bl0 = f2tf(f0 - __uint_as_float(bh0));
            unsigned bl1 = f2tf(f1 - __uint_as_float(bh1));
#pragma unroll
            for (int mt = 0; mt < 2; mt++) {
                // hi*lo and lo*hi corrections first, hi*hi last
                mma_tf32(acc[mt][q], ah[mt][0], ah[mt][1], ah[mt][2], ah[mt][3], bl0, bl1);
                mma_tf32(acc[mt][q], al[mt][0], al[mt][1], al[mt][2], al[mt][3], bh0, bh1);
                mma_tf32(acc[mt][q], ah[mt][0], ah[mt][1], ah[mt][2], ah[mt][3], bh0, bh1);
            }
        }
    }

    // Epilogue: u_hat fp32, [b][i][jd]; float2 stores (cols 2t,2t+1 contiguous)
#pragma unroll
    for (int mt = 0; mt < 2; mt++) {
        int b0r = mt * 16 + (lane >> 2);
#pragma unroll
        for (int q = 0; q < 4; q++) {
            int col = nbase + q * 8 + 2 * (lane & 3);
            *(float2*)(g_uhat + ((size_t)b0r * II + i) * JD + col) =
                make_float2(acc[mt][q][0], acc[mt][q][1]);
            *(float2*)(g_uhat + ((size_t)(b0r + 8) * II + i) * JD + col) =
                make_float2(acc[mt][q][2], acc[mt][q][3]);
        }
    }
}

// ---------------------------------------------------------------------------
// Kernel 2: partial sums over i of u_hat (route-1: c = 1/J uniform).
// ---------------------------------------------------------------------------
__global__ void reduce_uhat_kernel() {
    int idx = blockIdx.x * 256 + threadIdx.x;   // 0..16383 = b*512 + jd/4
    int ch  = blockIdx.y;
    int b   = idx >> 9, jd4 = idx & 511;
    const float4* p = (const float4*)(g_uhat + ((size_t)b * II + ch * ICH) * JD) + jd4;
    float4 s = make_float4(0.f, 0.f, 0.f, 0.f);
#pragma unroll 8
    for (int k = 0; k < ICH; k++) {
        float4 u = p[(size_t)k * (JD / 4)];
        s.x += u.x; s.y += u.y; s.z += u.z; s.w += u.w;
    }
    *(float4*)(&g_spart[ch][b * JD + jd4 * 4]) = s;
}

// ---------------------------------------------------------------------------
// Kernel 3: reduce partials + squash.  out==nullptr -> write g_v.
// ---------------------------------------------------------------------------
__global__ void squash_kernel(float scale, float* out) {
    int bj = blockIdx.x;
    int d  = threadIdx.x;
    float s = 0.f;
#pragma unroll
    for (int ch = 0; ch < NCHUNK; ch++) s += g_spart[ch][bj * 64 + d];
    s *= scale;

    float n2 = s * s;
#pragma unroll
    for (int off = 16; off; off >>= 1) n2 += __shfl_xor_sync(0xffffffffu, n2, off);
    __shared__ float tmp[2];
    if ((threadIdx.x & 31) == 0) tmp[threadIdx.x >> 5] = n2;
    __syncthreads();
    n2 = tmp[0] + tmp[1];

    float norm = sqrtf(n2);
    float f    = norm / (1.f + n2);
    float* dst = out ? out : g_v;
    dst[bj * 64 + d] = s * f;
}

// ---------------------------------------------------------------------------
// Kernel 4: fused agree + next-route partial-sum, register-resident.
// Thread t owns (j = t>>3, d = (t&7)*8 .. +7). One __syncthreads per i
// (double-buffered logit array). u loaded gmem->regs directly.
// ---------------------------------------------------------------------------
template <bool FIRST>
__global__ void __launch_bounds__(256)
route_kernel() {
    __shared__ float bj_s[2][JJ];

    const int b    = blockIdx.x;
    const int ch   = blockIdx.y;
    const int tid  = threadIdx.x;
    const int lane = tid & 31;
    const int j    = tid >> 3;        // 0..31
    const int d0   = (tid & 7) * 8;

    float v[8];
#pragma unroll
    for (int k = 0; k < 8; k++) v[k] = g_v[b * JD + j * 64 + d0 + k];

    float sacc[8] = {};

    for (int t = 0; t < ICH; t++) {
        const int i = ch * ICH + t;
        const size_t bidx = ((size_t)b * II + i) * JJ + j;
        const float* up = g_uhat + ((size_t)b * II + i) * JD + j * 64 + d0;

        float4 ua = *(const float4*)(up);
        float4 ub = *(const float4*)(up + 4);
        float b1v = FIRST ? 0.f : g_b1[bidx];   // broadcast within j-group

        float u[8] = {ua.x, ua.y, ua.z, ua.w, ub.x, ub.y, ub.z, ub.w};

        // agreement dot over this thread's 8 d's, then over the 8-lane j-group
        float dot = 0.f;
#pragma unroll
        for (int k = 0; k < 8; k++) dot = fmaf(u[k], v[k], dot);
        dot += __shfl_xor_sync(0xffffffffu, dot, 1);
        dot += __shfl_xor_sync(0xffffffffu, dot, 2);
        dot += __shfl_xor_sync(0xffffffffu, dot, 4);

        if ((lane & 7) == 0) {
            float bv = dot + b1v;
            if (FIRST) g_b1[bidx] = dot;      // b starts at 0 -> logit == dot
            bj_s[t & 1][j] = bv;
        }
        __syncthreads();

        // redundant per-warp softmax over the 32 logits
        float xv = bj_s[t & 1][lane];
        float m = xv;
#pragma unroll
        for (int off = 16; off; off >>= 1)
            m = fmaxf(m, __shfl_xor_sync(0xffffffffu, m, off));
        float e = __expf(xv - m);
        float ssum = e;
#pragma unroll
        for (int off = 16; off; off >>= 1)
            ssum += __shfl_xor_sync(0xffffffffu, ssum, off);
        float c = __shfl_sync(0xffffffffu, e / ssum, j);

#pragma unroll
        for (int k = 0; k < 8; k++) sacc[k] = fmaf(c, u[k], sacc[k]);
    }

    float* sp = &g_spart[ch][b * JD + tid * 8];
    *(float4*)(sp)     = make_float4(sacc[0], sacc[1], sacc[2], sacc[3]);
    *(float4*)(sp + 4) = make_float4(sacc[4], sacc[5], sacc[6], sacc[7]);
}

// ---------------------------------------------------------------------------
extern "C" void kernel_launch(void* const* d_in, const int* in_sizes, int n_in,
                              void* d_out, int out_size) {
    const float *x, *W;
    if (in_sizes[0] == BB * II * CC) { x = (const float*)d_in[0]; W = (const float*)d_in[1]; }
    else                             { x = (const float*)d_in[1]; W = (const float*)d_in[0]; }
    float* out = (float*)d_out;

    // 1) u_hat GEMM (tf32x3 MMA, fp32 output)
    gemm_kernel<<<dim3(8, II), 256>>>(x, W);
    // 2) s1 = sum_i u_hat (partials), v1 = squash(s1 / J)
    reduce_uhat_kernel<<<dim3(BB * JD / 4 / 256, NCHUNK), 256>>>();
    squash_kernel<<<BB * JJ, 64>>>(1.0f / (float)JJ, nullptr);
    // 3) agree1 + route2 partials; v2 = squash(s2)
    route_kernel<true><<<dim3(BB, NCHUNK), 256>>>();
    squash_kernel<<<BB * JJ, 64>>>(1.0f, nullptr);
    // 4) agree2 + route3 partials; output = squash(s3)
    route_kernel<false><<<dim3(BB, NCHUNK), 256>>>();
    squash_kernel<<<BB * JJ, 64>>>(1.0f, out);
}

// round 6
// speedup vs baseline: 1.2727x; 1.2727x over previous
#include <cuda_runtime.h>
#include <cuda_fp16.h>
#include <math.h>

#define BB 32
#define II 1024
#define CC 128
#define JJ 32
#define DD 64
#define JD 2048           // JJ*DD
#define NCHUNK 32
#define ICH (II/NCHUNK)   // 32 i's per chunk

// Scratch (device globals: no allocation in kernel_launch)
__device__ float g_uhat[(size_t)BB * II * JD];   // [b][i][j*64+d], 256 MiB
__device__ float g_spart[NCHUNK][BB * JD];       // partial s sums, 8 MiB
__device__ float g_b1[(size_t)BB * II * JJ];     // routing logits after agree1, 4 MiB
__device__ float g_v[BB * JD];                   // current v[b][j][d]

// ---------------------------------------------------------------------------
// fp16 mma helper (m16n8k16, fp32 accumulate)
// ---------------------------------------------------------------------------
__device__ __forceinline__ void mma_f16(float c[4],
                                        unsigned a0, unsigned a1, unsigned a2, unsigned a3,
                                        unsigned b0, unsigned b1) {
    asm volatile(
        "mma.sync.aligned.m16n8k16.row.col.f32.f16.f16.f32 "
        "{%0,%1,%2,%3}, {%4,%5,%6,%7}, {%8,%9}, {%0,%1,%2,%3};"
        : "+f"(c[0]), "+f"(c[1]), "+f"(c[2]), "+f"(c[3])
        : "r"(a0), "r"(a1), "r"(a2), "r"(a3), "r"(b0), "r"(b1));
}

__device__ __forceinline__ unsigned h2u(__half2 h) {
    return *reinterpret_cast<unsigned*>(&h);
}

// split float2 into fp16 hi + fp16 lo (Markidis), packed half2
__device__ __forceinline__ void split2(float2 w, unsigned& hi, unsigned& lo) {
    __half2 h = __floats2half2_rn(w.x, w.y);
    float2 r = make_float2(w.x - __low2float(h), w.y - __high2float(h));
    __half2 l = __floats2half2_rn(r.x, r.y);
    hi = h2u(h); lo = h2u(l);
}

// ---------------------------------------------------------------------------
// Kernel 1: u_hat GEMM, fp16x3 error-compensated (~fp32 accuracy).
// Per block: one i, 256-wide jd tile, all 32 b (M=32, N=256, K=128).
// A (x slice) staged in smem split hi/lo fp16; B (W) streamed from global
// as float2 (read exactly once), split hi/lo in registers, depth-1 prefetch.
// ---------------------------------------------------------------------------
#define XS 136   // half-stride per row: conflict-free half2 fragment reads

__global__ void __launch_bounds__(256, 2)
gemm_kernel(const float* __restrict__ x, const float* __restrict__ W) {
    __shared__ __half xh[32 * XS];
    __shared__ __half xl[32 * XS];

    const int i    = blockIdx.y;
    const int jt   = blockIdx.x;          // 0..7 -> jd base = jt*256
    const int tid  = threadIdx.x;
    const int lane = tid & 31;
    const int warp = tid >> 5;

    // Stage x[:, i, :] split into fp16 hi/lo, row-major [b][c]
    for (int e = tid * 4; e < BB * CC; e += 1024) {
        int b = e >> 7, c = e & 127;
        float4 v = *(const float4*)(x + ((size_t)b * II + i) * CC + c);
        float f[4] = {v.x, v.y, v.z, v.w};
#pragma unroll
        for (int k = 0; k < 4; k++) {
            __half h = __float2half_rn(f[k]);
            xh[b * XS + c + k] = h;
            xl[b * XS + c + k] = __float2half_rn(f[k] - __half2float(h));
        }
    }
    __syncthreads();

    const int nbase = jt * 256 + warp * 32;   // this warp's jd base (32 wide)
    const float2* Wp[4];
#pragma unroll
    for (int q = 0; q < 4; q++) {
        int n = nbase + q * 8 + (lane >> 2);
        int j = n >> 6, d = n & 63;
        // + (lane&3) float2 = element offset (lane&3)*2 within the 128-c row
        Wp[q] = (const float2*)(W + (((size_t)j * II + i) * DD + d) * CC) + (lane & 3);
    }

    float acc[2][4][4] = {};
    float2 bf[2][4][2];
#pragma unroll
    for (int q = 0; q < 4; q++) { bf[0][q][0] = Wp[q][0]; bf[0][q][1] = Wp[q][4]; }

    const int arow = lane >> 2;
    const int acol = lane & 3;

#pragma unroll
    for (int s = 0; s < 8; s++) {          // K = 8 steps of 16
        const int cur = s & 1, nxt = cur ^ 1;
        if (s < 7) {
#pragma unroll
            for (int q = 0; q < 4; q++) {
                bf[nxt][q][0] = Wp[q][8 * (s + 1)];
                bf[nxt][q][1] = Wp[q][8 * (s + 1) + 4];
            }
        }
        // A fragments (hi and lo), half2-packed
        unsigned ah[2][4], al[2][4];
#pragma unroll
        for (int mt = 0; mt < 2; mt++) {
            const int base = (mt * 16 + arow) * XS + s * 16 + acol * 2;
            ah[mt][0] = h2u(*(const __half2*)(xh + base));
            ah[mt][1] = h2u(*(const __half2*)(xh + base + 8 * XS));
            ah[mt][2] = h2u(*(const __half2*)(xh + base + 8));
            ah[mt][3] = h2u(*(const __half2*)(xh + base + 8 * XS + 8));
            al[mt][0] = h2u(*(const __half2*)(xl + base));
            al[mt][1] = h2u(*(const __half2*)(xl + base + 8 * XS));
            al[mt][2] = h2u(*(const __half2*)(xl + base + 8));
            al[mt][3] = h2u(*(const __half2*)(xl + base + 8 * XS + 8));
        }
#pragma unroll
        for (int q = 0; q < 4; q++) {
            unsigned bh0, bl0, bh1, bl1;
            split2(bf[cur][q][0], bh0, bl0);
            split2(bf[cur][q][1], bh1, bl1);
#pragma unroll
            for (int mt = 0; mt < 2; mt++) {
                mma_f16(acc[mt][q], ah[mt][0], ah[mt][1], ah[mt][2], ah[mt][3], bl0, bl1);
                mma_f16(acc[mt][q], al[mt][0], al[mt][1], al[mt][2], al[mt][3], bh0, bh1);
                mma_f16(acc[mt][q], ah[mt][0], ah[mt][1], ah[mt][2], ah[mt][3], bh0, bh1);
            }
        }
    }

    // Epilogue: u_hat fp32, [b][i][jd]; float2 stores (cols 2t,2t+1 contiguous)
#pragma unroll
    for (int mt = 0; mt < 2; mt++) {
        int b0r = mt * 16 + (lane >> 2);
#pragma unroll
        for (int q = 0; q < 4; q++) {
            int col = nbase + q * 8 + 2 * (lane & 3);
            *(float2*)(g_uhat + ((size_t)b0r * II + i) * JD + col) =
                make_float2(acc[mt][q][0], acc[mt][q][1]);
            *(float2*)(g_uhat + ((size_t)(b0r + 8) * II + i) * JD + col) =
                make_float2(acc[mt][q][2], acc[mt][q][3]);
        }
    }
}

// ---------------------------------------------------------------------------
// Kernel 2: partial sums over i of u_hat (route-1: c = 1/J uniform).
// ---------------------------------------------------------------------------
__global__ void reduce_uhat_kernel() {
    int idx = blockIdx.x * 256 + threadIdx.x;   // 0..16383 = b*512 + jd/4
    int ch  = blockIdx.y;
    int b   = idx >> 9, jd4 = idx & 511;
    const float4* p = (const float4*)(g_uhat + ((size_t)b * II + ch * ICH) * JD) + jd4;
    float4 s = make_float4(0.f, 0.f, 0.f, 0.f);
#pragma unroll 8
    for (int k = 0; k < ICH; k++) {
        float4 u = p[(size_t)k * (JD / 4)];
        s.x += u.x; s.y += u.y; s.z += u.z; s.w += u.w;
    }
    *(float4*)(&g_spart[ch][b * JD + jd4 * 4]) = s;
}

// ---------------------------------------------------------------------------
// Kernel 3: reduce partials + squash.  out==nullptr -> write g_v.
// ---------------------------------------------------------------------------
__global__ void squash_kernel(float scale, float* out) {
    int bj = blockIdx.x;
    int d  = threadIdx.x;
    float s = 0.f;
#pragma unroll
    for (int ch = 0; ch < NCHUNK; ch++) s += g_spart[ch][bj * 64 + d];
    s *= scale;

    float n2 = s * s;
#pragma unroll
    for (int off = 16; off; off >>= 1) n2 += __shfl_xor_sync(0xffffffffu, n2, off);
    __shared__ float tmp[2];
    if ((threadIdx.x & 31) == 0) tmp[threadIdx.x >> 5] = n2;
    __syncthreads();
    n2 = tmp[0] + tmp[1];

    float norm = sqrtf(n2);
    float f    = norm / (1.f + n2);
    float* dst = out ? out : g_v;
    dst[bj * 64 + d] = s * f;
}

// ---------------------------------------------------------------------------
// Kernel 4: fused agree + next-route partial-sum, register-resident,
// 2-way i-unroll (one barrier per 2 i's, 4-slot logit ring) with software
// prefetch of the next pair's u/b1 issued right after the barrier.
// Thread t owns (j = t>>3, d = (t&7)*8 .. +7).
// ---------------------------------------------------------------------------
template <bool FIRST>
__global__ void __launch_bounds__(256)
route_kernel() {
    __shared__ float bj_s[4][JJ];

    const int b    = blockIdx.x;
    const int ch   = blockIdx.y;
    const int tid  = threadIdx.x;
    const int lane = tid & 31;
    const int j    = tid >> 3;        // 0..31
    const int d0   = (tid & 7) * 8;

    float v[8];
#pragma unroll
    for (int k = 0; k < 8; k++) v[k] = g_v[b * JD + j * 64 + d0 + k];

    const float* ub = g_uhat + ((size_t)b * II + ch * ICH) * JD + j * 64 + d0;
    const float* bb = g_b1 + ((size_t)b * II + ch * ICH) * JJ + j;
    float* bw       = g_b1 + ((size_t)b * II + ch * ICH) * JJ + j;

    float sacc[8] = {};
    float u[2][8];
    float b1v[2];

    // prologue: load t = 0, 1
#pragma unroll
    for (int r = 0; r < 2; r++) {
        float4 a = *(const float4*)(ub + (size_t)r * JD);
        float4 c = *(const float4*)(ub + (size_t)r * JD + 4);
        u[r][0]=a.x; u[r][1]=a.y; u[r][2]=a.z; u[r][3]=a.w;
        u[r][4]=c.x; u[r][5]=c.y; u[r][6]=c.z; u[r][7]=c.w;
        b1v[r] = FIRST ? 0.f : bb[(size_t)r * JJ];
    }

#pragma unroll
    for (int p = 0; p < ICH / 2; p++) {
        // agreement dots for both i's of this pair
#pragma unroll
        for (int r = 0; r < 2; r++) {
            const int t = 2 * p + r;
            float dot = 0.f;
#pragma unroll
            for (int k = 0; k < 8; k++) dot = fmaf(u[r][k], v[k], dot);
            dot += __shfl_xor_sync(0xffffffffu, dot, 1);
            dot += __shfl_xor_sync(0xffffffffu, dot, 2);
            dot += __shfl_xor_sync(0xffffffffu, dot, 4);
            if ((lane & 7) == 0) {
                if (FIRST) bw[(size_t)t * JJ] = dot;   // b starts at 0 -> logit == dot
                bj_s[t & 3][j] = dot + b1v[r];
            }
        }
        __syncthreads();

        // prefetch next pair (overlaps the softmax chains below)
        float un[2][8];
        float b1n[2];
        if (p + 1 < ICH / 2) {
#pragma unroll
            for (int r = 0; r < 2; r++) {
                const size_t t = 2 * p + 2 + r;
                float4 a = *(const float4*)(ub + t * JD);
                float4 c = *(const float4*)(ub + t * JD + 4);
                un[r][0]=a.x; un[r][1]=a.y; un[r][2]=a.z; un[r][3]=a.w;
                un[r][4]=c.x; un[r][5]=c.y; un[r][6]=c.z; un[r][7]=c.w;
                b1n[r] = FIRST ? 0.f : bb[t * JJ];
            }
        }

        // redundant per-warp softmax + accumulate, both i's
#pragma unroll
        for (int r = 0; r < 2; r++) {
            const int t = 2 * p + r;
            float xv = bj_s[t & 3][lane];
            float m = xv;
#pragma unroll
            for (int off = 16; off; off >>= 1)
                m = fmaxf(m, __shfl_xor_sync(0xffffffffu, m, off));
            float e = __expf(xv - m);
            float ssum = e;
#pragma unroll
            for (int off = 16; off; off >>= 1)
                ssum += __shfl_xor_sync(0xffffffffu, ssum, off);
            float c = __shfl_sync(0xffffffffu, e / ssum, j);
#pragma unroll
            for (int k = 0; k < 8; k++) sacc[k] = fmaf(c, u[r][k], sacc[k]);
        }

        if (p + 1 < ICH / 2) {
#pragma unroll
            for (int r = 0; r < 2; r++) {
#pragma unroll
                for (int k = 0; k < 8; k++) u[r][k] = un[r][k];
                b1v[r] = b1n[r];
            }
        }
    }

    float* sp = &g_spart[ch][b * JD + tid * 8];
    *(float4*)(sp)     = make_float4(sacc[0], sacc[1], sacc[2], sacc[3]);
    *(float4*)(sp + 4) = make_float4(sacc[4], sacc[5], sacc[6], sacc[7]);
}

// ---------------------------------------------------------------------------
extern "C" void kernel_launch(void* const* d_in, const int* in_sizes, int n_in,
                              void* d_out, int out_size) {
    const float *x, *W;
    if (in_sizes[0] == BB * II * CC) { x = (const float*)d_in[0]; W = (const float*)d_in[1]; }
    else                             { x = (const float*)d_in[1]; W = (const float*)d_in[0]; }
    float* out = (float*)d_out;

    // 1) u_hat GEMM (fp16x3 MMA, fp32 output)
    gemm_kernel<<<dim3(8, II), 256>>>(x, W);
    // 2) s1 = sum_i u_hat (partials), v1 = squash(s1 / J)
    reduce_uhat_kernel<<<dim3(BB * JD / 4 / 256, NCHUNK), 256>>>();
    squash_kernel<<<BB * JJ, 64>>>(1.0f / (float)JJ, nullptr);
    // 3) agree1 + route2 partials; v2 = squash(s2)
    route_kernel<true><<<dim3(BB, NCHUNK), 256>>>();
    squash_kernel<<<BB * JJ, 64>>>(1.0f, nullptr);
    // 4) agree2 + route3 partials; output = squash(s3)
    route_kernel<false><<<dim3(BB, NCHUNK), 256>>>();
    squash_kernel<<<BB * JJ, 64>>>(1.0f, out);
}